// round 6
// baseline (speedup 1.0000x reference)
#include <cuda_runtime.h>
#include <cuda_fp16.h>
#include <math.h>
#include <float.h>

#define NN 80000
#define EE 1280000
#define GG 64
#define CINC 128
#define DD 64
#define NHID 5
#define NB_SCAN ((NN + 1023) / 1024)

typedef unsigned long long u64t;

__device__ __forceinline__ u64t fma2(u64t a, u64t b, u64t c) {
    u64t d;
    asm("fma.rn.f32x2 %0, %1, %2, %3;" : "=l"(d) : "l"(a), "l"(b), "l"(c));
    return d;
}
__device__ __forceinline__ u64t dup2(float x) {
    u64t r;
    unsigned xb = __float_as_uint(x);
    asm("mov.b64 %0, {%1, %1};" : "=l"(r) : "r"(xb));
    return r;
}

// ---------------- scratch ----------------
__device__ int    g_deg[NN];
__device__ float  g_dinv[NN];
__device__ int    g_rowptr[NN + 1];
__device__ int    g_cursor[NN];
__device__ int2   g_edge[EE];        // {src, wnorm bits}
__device__ __half2 g_h0h[NN * 32];   // GEMM output (fp16, gather source)
__device__ float  g_h1[NN * DD];     // aggregation output (fp32)
__device__ int    g_bsum[NB_SCAN];
__device__ int    g_boff[NB_SCAN];
__device__ int    g_scan_done;

// ---------------- CSR build ----------------
__global__ void zero_deg_kernel() {
    int i = blockIdx.x * blockDim.x + threadIdx.x;
    if (i < NN) g_deg[i] = 0;
    if (i == 0) g_scan_done = 0;
}

__global__ void count_deg_kernel(const int* __restrict__ ei) {
    int e = blockIdx.x * blockDim.x + threadIdx.x;
    if (e < EE) atomicAdd(&g_deg[ei[EE + e]], 1);
}

// per-block scan + dinv; LAST block to finish also scans the block sums
__global__ void scanAB_kernel() {
    __shared__ int sh[1024];
    int gid = blockIdx.x * 1024 + threadIdx.x;
    int v = (gid < NN) ? g_deg[gid] : 0;
    if (gid < NN) g_dinv[gid] = rsqrtf((float)(v + 1));
    sh[threadIdx.x] = v;
    __syncthreads();
    #pragma unroll
    for (int off = 1; off < 1024; off <<= 1) {
        int t = (threadIdx.x >= off) ? sh[threadIdx.x - off] : 0;
        __syncthreads();
        sh[threadIdx.x] += t;
        __syncthreads();
    }
    if (gid < NN) g_rowptr[gid] = sh[threadIdx.x] - v;
    if (threadIdx.x == 1023) g_bsum[blockIdx.x] = sh[1023];

    // last-block-done: scan block sums
    __shared__ int s_last;
    __threadfence();
    if (threadIdx.x == 0)
        s_last = (atomicAdd(&g_scan_done, 1) == NB_SCAN - 1);
    __syncthreads();
    if (s_last && threadIdx.x < 128) {
        int t = threadIdx.x;
        int bv = (t < NB_SCAN) ? g_bsum[t] : 0;
        sh[t] = bv;
        __syncwarp();  // need block sync among 128 threads:
        __syncthreads();
        #pragma unroll
        for (int off = 1; off < 128; off <<= 1) {
            int u = (t >= off) ? sh[t - off] : 0;
            __syncthreads();
            sh[t] += u;
            __syncthreads();
        }
        if (t < NB_SCAN) g_boff[t] = sh[t] - bv;
    } else if (s_last) {
        // non-participating threads of last block must join the barriers
        __syncthreads();
        #pragma unroll
        for (int off = 1; off < 128; off <<= 1) {
            __syncthreads();
            __syncthreads();
        }
    }
}

__global__ void scanC_kernel() {
    int gid = blockIdx.x * 1024 + threadIdx.x;
    if (gid < NN) {
        int r = g_rowptr[gid] + g_boff[blockIdx.x];
        g_rowptr[gid] = r;
        g_cursor[gid] = r;
    }
    if (gid == 0) g_rowptr[NN] = EE;
}

__global__ void scatter_kernel(const int* __restrict__ ei) {
    int e = blockIdx.x * blockDim.x + threadIdx.x;
    if (e < EE) {
        int s = ei[e];
        int d = ei[EE + e];
        int pos = atomicAdd(&g_cursor[d], 1);
        float w = g_dinv[s] * g_dinv[d];
        g_edge[pos] = make_int2(s, __float_as_int(w));
    }
}

// ------ Tiled GEMM: g_h0h[N,64](fp16) = X[N,K](fp32) @ W[K,64] -----------
template <int K, bool FROM_EXT>
__global__ __launch_bounds__(128) void gemm_kernel(const float* __restrict__ X,
                                                   const float* __restrict__ W) {
    extern __shared__ char smem_raw[];
    u64t*  Ws = reinterpret_cast<u64t*>(smem_raw);
    float* Xs = reinterpret_cast<float*>(smem_raw + (size_t)K * 32 * 8);
    const int XS_LD = K + 1;

    int tid = threadIdx.x;

    {
        const u64t* Wg = reinterpret_cast<const u64t*>(W);
        #pragma unroll
        for (int i = tid; i < K * 32; i += 128) Ws[i] = Wg[i];
    }
    {
        const float* xb =
            (FROM_EXT ? X : (const float*)g_h1) + (size_t)blockIdx.x * 128 * K;
        #pragma unroll
        for (int i = tid; i < 128 * K; i += 128) {
            int r = i / K;
            int k = i - r * K;
            Xs[r * XS_LD + k] = xb[i];
        }
    }
    __syncthreads();

    int colg = tid & 7;
    int rowg = tid >> 3;

    u64t acc[32];
    #pragma unroll
    for (int j = 0; j < 32; j++) acc[j] = 0ull;

    const float* xrow = Xs + rowg * 8 * XS_LD;
    const ulonglong2* wsp =
        reinterpret_cast<const ulonglong2*>(Ws + colg * 4);

    #pragma unroll 4
    for (int k = 0; k < K; k++) {
        ulonglong2 wa = wsp[k * 16];
        ulonglong2 wb = wsp[k * 16 + 1];
        #pragma unroll
        for (int r = 0; r < 8; r++) {
            u64t xd = dup2(xrow[r * XS_LD + k]);
            acc[r * 4 + 0] = fma2(wa.x, xd, acc[r * 4 + 0]);
            acc[r * 4 + 1] = fma2(wa.y, xd, acc[r * 4 + 1]);
            acc[r * 4 + 2] = fma2(wb.x, xd, acc[r * 4 + 2]);
            acc[r * 4 + 3] = fma2(wb.y, xd, acc[r * 4 + 3]);
        }
    }

    size_t rowbase = (size_t)blockIdx.x * 128 + rowg * 8;
    #pragma unroll
    for (int r = 0; r < 8; r++) {
        unsigned h[4];
        #pragma unroll
        for (int p = 0; p < 4; p++) {
            unsigned lo, hi;
            asm("mov.b64 {%0, %1}, %2;" : "=r"(lo), "=r"(hi) : "l"(acc[r * 4 + p]));
            __half2 hh = __floats2half2_rn(__uint_as_float(lo), __uint_as_float(hi));
            h[p] = *reinterpret_cast<unsigned*>(&hh);
        }
        uint4 o = make_uint4(h[0], h[1], h[2], h[3]);
        *reinterpret_cast<uint4*>(
            reinterpret_cast<char*>(g_h0h) + (rowbase + r) * 128 + colg * 16) = o;
    }
}

// ------ aggregation: warp/node, lane-parallel edge prefetch + shfl --------
__global__ void aggregate_kernel(const float* __restrict__ bias, int relu) {
    int node = blockIdx.x * (blockDim.x >> 5) + (threadIdx.x >> 5);
    int lane = threadIdx.x & 31;
    if (node >= NN) return;

    float dn = g_dinv[node];
    float sw = dn * dn;
    float2 self = __half22float2(g_h0h[(size_t)node * 32 + lane]);
    float ax = sw * self.x;
    float ay = sw * self.y;

    int beg = g_rowptr[node];
    int end = g_rowptr[node + 1];

    for (int base = beg; base < end; base += 32) {
        int e = base + lane;
        int2 ed = make_int2(0, 0);
        if (e < end) ed = __ldg(&g_edge[e]);
        int cnt = min(32, end - base);
        #pragma unroll 4
        for (int i = 0; i < cnt; i++) {
            int   src = __shfl_sync(0xFFFFFFFF, ed.x, i);
            float ww  = __int_as_float(__shfl_sync(0xFFFFFFFF, ed.y, i));
            float2 hv = __half22float2(g_h0h[(size_t)src * 32 + lane]);
            ax += ww * hv.x;
            ay += ww * hv.y;
        }
    }

    float2 bv = reinterpret_cast<const float2*>(bias)[lane];
    ax += bv.x;
    ay += bv.y;
    if (relu) { ax = fmaxf(ax, 0.f); ay = fmaxf(ay, 0.f); }
    reinterpret_cast<float2*>(g_h1)[(size_t)node * 32 + lane] =
        make_float2(ax, ay);
}

// ---------------- fused pooling + MLP head ----------------
__global__ __launch_bounds__(256) void pool_head_kernel(
        const int* __restrict__ batch,
        const float* __restrict__ lin1_w, const float* __restrict__ lin1_b,
        const float* __restrict__ lin2_w, const float* __restrict__ lin2_b,
        const float* __restrict__ lin3_w, const float* __restrict__ lin3_b,
        float* __restrict__ out) {
    int g = blockIdx.x;
    int tid = threadIdx.x;
    __shared__ int s_se[2];

    if (tid < 2) {
        int target = g + tid;
        int lo = 0, hi = NN;
        while (lo < hi) {
            int mid = (lo + hi) >> 1;
            if (__ldg(&batch[mid]) < target) lo = mid + 1;
            else hi = mid;
        }
        s_se[tid] = lo;
    }
    __syncthreads();
    int start = s_se[0], end = s_se[1];

    int sub = tid >> 6;
    int d   = tid & 63;

    float sum = 0.f, mx = -FLT_MAX;
    for (int n = start + sub; n < end; n += 4) {
        float v = g_h1[(size_t)n * 64 + d];
        sum += v;
        mx = fmaxf(mx, v);
    }

    __shared__ float ssum[4][64];
    __shared__ float smax[4][64];
    __shared__ float feat[128];
    __shared__ float s1[64];
    __shared__ float s2[64];
    __shared__ float red[64];

    ssum[sub][d] = sum;
    smax[sub][d] = mx;
    __syncthreads();

    if (tid < 64) {
        feat[d]      = ssum[0][d] + ssum[1][d] + ssum[2][d] + ssum[3][d];
        feat[64 + d] = fmaxf(fmaxf(smax[0][d], smax[1][d]),
                             fmaxf(smax[2][d], smax[3][d]));
    }
    __syncthreads();

    if (tid < 64) {
        float a = lin1_b[d];
        #pragma unroll 8
        for (int k = 0; k < 128; k++) a += feat[k] * lin1_w[k * 64 + d];
        s1[d] = fmaxf(a, 0.f);
    }
    __syncthreads();
    if (tid < 64) {
        float b = lin2_b[d];
        #pragma unroll 8
        for (int k = 0; k < 64; k++) b += s1[k] * lin2_w[k * 64 + d];
        s2[d] = fmaxf(b, 0.f);
        red[d] = s2[d] * lin3_w[d];
    }
    __syncthreads();
    if (tid < 32) {
        float v = red[tid] + red[tid + 32];
        #pragma unroll
        for (int off = 16; off > 0; off >>= 1)
            v += __shfl_down_sync(0xFFFFFFFF, v, off);
        if (tid == 0) out[g] = v + lin3_b[0];
    }
}

// ---------------- launch ----------------
#define SMEM_G64  (64 * 32 * 8 + 128 * 65 * 4)
#define SMEM_G128 (128 * 32 * 8 + 128 * 129 * 4)

extern "C" void kernel_launch(void* const* d_in, const int* in_sizes, int n_in,
                              void* d_out, int out_size) {
    const float* x      = (const float*)d_in[0];
    const int*   ei     = (const int*)d_in[1];
    const int*   batch  = (const int*)d_in[2];
    const float* W_in   = (const float*)d_in[3];
    const float* b_in   = (const float*)d_in[4];
    const float* W_hid  = (const float*)d_in[5];
    const float* b_hid  = (const float*)d_in[6];
    const float* lin1_w = (const float*)d_in[7];
    const float* lin1_b = (const float*)d_in[8];
    const float* lin2_w = (const float*)d_in[9];
    const float* lin2_b = (const float*)d_in[10];
    const float* lin3_w = (const float*)d_in[11];
    const float* lin3_b = (const float*)d_in[12];
    float* out = (float*)d_out;

    cudaFuncSetAttribute(gemm_kernel<CINC, true>,
                         cudaFuncAttributeMaxDynamicSharedMemorySize, SMEM_G128);
    cudaFuncSetAttribute(gemm_kernel<DD, false>,
                         cudaFuncAttributeMaxDynamicSharedMemorySize, SMEM_G64);

    // CSR build: launches 0..4
    zero_deg_kernel<<<(NN + 255) / 256, 256>>>();
    count_deg_kernel<<<(EE + 255) / 256, 256>>>(ei);
    scanAB_kernel<<<NB_SCAN, 1024>>>();
    scanC_kernel<<<NB_SCAN, 1024>>>();
    scatter_kernel<<<(EE + 255) / 256, 256>>>(ei);

    const int gemm_blocks = NN / 128;
    const int agg_blocks  = (NN + 7) / 8;

    // launch #5 = input GEMM (profiled by ncu -s 5 -c 1)
    gemm_kernel<CINC, true><<<gemm_blocks, 128, SMEM_G128>>>(x, W_in);
    aggregate_kernel<<<agg_blocks, 256>>>(b_in, 1);

    for (int i = 0; i < NHID; i++) {
        gemm_kernel<DD, false><<<gemm_blocks, 128, SMEM_G64>>>(
            nullptr, W_hid + (size_t)i * DD * DD);
        aggregate_kernel<<<agg_blocks, 256>>>(b_hid + (size_t)i * DD,
                                              (i < NHID - 1) ? 1 : 0);
    }

    pool_head_kernel<<<GG, 256>>>(batch, lin1_w, lin1_b, lin2_w, lin2_b,
                                  lin3_w, lin3_b, out);
}

// round 7
// speedup vs baseline: 1.1558x; 1.1558x over previous
#include <cuda_runtime.h>
#include <cuda_fp16.h>
#include <math.h>
#include <float.h>

#define NN 80000
#define EE 1280000
#define GG 64
#define CINC 128
#define DD 64
#define NHID 5
#define NB_SCAN ((NN + 1023) / 1024)

typedef unsigned long long u64t;

__device__ __forceinline__ u64t fma2(u64t a, u64t b, u64t c) {
    u64t d;
    asm("fma.rn.f32x2 %0, %1, %2, %3;" : "=l"(d) : "l"(a), "l"(b), "l"(c));
    return d;
}
__device__ __forceinline__ u64t dup2(float x) {
    u64t r;
    unsigned xb = __float_as_uint(x);
    asm("mov.b64 %0, {%1, %1};" : "=l"(r) : "r"(xb));
    return r;
}

// ---------------- scratch ----------------
__device__ int    g_deg[NN];
__device__ float  g_dinv[NN];
__device__ int    g_rowptr[NN + 1];
__device__ int    g_cursor[NN];
__device__ int2   g_edge[EE];        // {src, wnorm bits}
__device__ __half2 g_h0h[NN * 32];   // GEMM output (fp16, gather source)
__device__ float  g_h1[NN * DD];     // aggregation output (fp32)
__device__ int    g_bsum[NB_SCAN];
__device__ int    g_boff[NB_SCAN];
__device__ int    g_scan_done;

// ---------------- CSR build ----------------
__global__ void zero_deg_kernel() {
    int i = blockIdx.x * blockDim.x + threadIdx.x;
    if (i < NN) g_deg[i] = 0;
    if (i == 0) g_scan_done = 0;
}

__global__ void count_deg_kernel(const int* __restrict__ ei) {
    int e = blockIdx.x * blockDim.x + threadIdx.x;
    if (e < EE) atomicAdd(&g_deg[ei[EE + e]], 1);
}

// per-block scan + dinv; LAST block to finish also scans the block sums
__global__ void scanAB_kernel() {
    __shared__ int sh[1024];
    int gid = blockIdx.x * 1024 + threadIdx.x;
    int v = (gid < NN) ? g_deg[gid] : 0;
    if (gid < NN) g_dinv[gid] = rsqrtf((float)(v + 1));
    sh[threadIdx.x] = v;
    __syncthreads();
    #pragma unroll
    for (int off = 1; off < 1024; off <<= 1) {
        int t = (threadIdx.x >= off) ? sh[threadIdx.x - off] : 0;
        __syncthreads();
        sh[threadIdx.x] += t;
        __syncthreads();
    }
    if (gid < NN) g_rowptr[gid] = sh[threadIdx.x] - v;
    if (threadIdx.x == 1023) g_bsum[blockIdx.x] = sh[1023];

    __shared__ int s_last;
    __threadfence();
    if (threadIdx.x == 0)
        s_last = (atomicAdd(&g_scan_done, 1) == NB_SCAN - 1);
    __syncthreads();
    if (s_last) {
        int t = threadIdx.x;
        int bv = (t < NB_SCAN) ? g_bsum[t] : 0;
        if (t < 128) sh[t] = bv;
        __syncthreads();
        #pragma unroll
        for (int off = 1; off < 128; off <<= 1) {
            int u = (t >= off && t < 128) ? sh[t - off] : 0;
            __syncthreads();
            if (t < 128) sh[t] += u;
            __syncthreads();
        }
        if (t < NB_SCAN) g_boff[t] = sh[t] - bv;
    }
}

__global__ void scanC_kernel() {
    int gid = blockIdx.x * 1024 + threadIdx.x;
    if (gid < NN) {
        int r = g_rowptr[gid] + g_boff[blockIdx.x];
        g_rowptr[gid] = r;
        g_cursor[gid] = r;
    }
    if (gid == 0) g_rowptr[NN] = EE;
}

__global__ void scatter_kernel(const int* __restrict__ ei) {
    int e = blockIdx.x * blockDim.x + threadIdx.x;
    if (e < EE) {
        int s = ei[e];
        int d = ei[EE + e];
        int pos = atomicAdd(&g_cursor[d], 1);
        float w = g_dinv[s] * g_dinv[d];
        g_edge[pos] = make_int2(s, __float_as_int(w));
    }
}

// ------ Tiled GEMM: g_h0h[N,64](fp16) = X[N,K](fp32) @ W[K,64] -----------
template <int K, bool FROM_EXT>
__global__ __launch_bounds__(128) void gemm_kernel(const float* __restrict__ X,
                                                   const float* __restrict__ W) {
    extern __shared__ char smem_raw[];
    u64t*  Ws = reinterpret_cast<u64t*>(smem_raw);
    float* Xs = reinterpret_cast<float*>(smem_raw + (size_t)K * 32 * 8);
    const int XS_LD = K + 1;

    int tid = threadIdx.x;

    {
        const u64t* Wg = reinterpret_cast<const u64t*>(W);
        #pragma unroll
        for (int i = tid; i < K * 32; i += 128) Ws[i] = Wg[i];
    }
    {
        const float* xb =
            (FROM_EXT ? X : (const float*)g_h1) + (size_t)blockIdx.x * 128 * K;
        #pragma unroll
        for (int i = tid; i < 128 * K; i += 128) {
            int r = i / K;
            int k = i - r * K;
            Xs[r * XS_LD + k] = xb[i];
        }
    }
    __syncthreads();

    int colg = tid & 7;
    int rowg = tid >> 3;

    u64t acc[32];
    #pragma unroll
    for (int j = 0; j < 32; j++) acc[j] = 0ull;

    const float* xrow = Xs + rowg * 8 * XS_LD;
    const ulonglong2* wsp =
        reinterpret_cast<const ulonglong2*>(Ws + colg * 4);

    #pragma unroll 4
    for (int k = 0; k < K; k++) {
        ulonglong2 wa = wsp[k * 16];
        ulonglong2 wb = wsp[k * 16 + 1];
        #pragma unroll
        for (int r = 0; r < 8; r++) {
            u64t xd = dup2(xrow[r * XS_LD + k]);
            acc[r * 4 + 0] = fma2(wa.x, xd, acc[r * 4 + 0]);
            acc[r * 4 + 1] = fma2(wa.y, xd, acc[r * 4 + 1]);
            acc[r * 4 + 2] = fma2(wb.x, xd, acc[r * 4 + 2]);
            acc[r * 4 + 3] = fma2(wb.y, xd, acc[r * 4 + 3]);
        }
    }

    size_t rowbase = (size_t)blockIdx.x * 128 + rowg * 8;
    #pragma unroll
    for (int r = 0; r < 8; r++) {
        unsigned h[4];
        #pragma unroll
        for (int p = 0; p < 4; p++) {
            unsigned lo, hi;
            asm("mov.b64 {%0, %1}, %2;" : "=r"(lo), "=r"(hi) : "l"(acc[r * 4 + p]));
            __half2 hh = __floats2half2_rn(__uint_as_float(lo), __uint_as_float(hi));
            h[p] = *reinterpret_cast<unsigned*>(&hh);
        }
        uint4 o = make_uint4(h[0], h[1], h[2], h[3]);
        *reinterpret_cast<uint4*>(
            reinterpret_cast<char*>(g_h0h) + (rowbase + r) * 128 + colg * 16) = o;
    }
}

// ------ aggregation: HALF-warp per node, uint2 (8B) per lane ---------------
// 1 gather LDG instruction covers 2 edges (one per half); 1 uniform edge LDG
// covers both halves -> ~1 LDG instr per edge (was 2).
__global__ void aggregate_kernel(const float* __restrict__ bias, int relu) {
    int warp = blockIdx.x * (blockDim.x >> 5) + (threadIdx.x >> 5);
    int half = (threadIdx.x >> 4) & 1;
    int hl   = threadIdx.x & 15;          // lane within half
    int node = warp * 2 + half;
    if (node >= NN) return;

    const uint2* h0 = reinterpret_cast<const uint2*>(g_h0h);  // 16 uint2/row

    float dn = g_dinv[node];
    float sw = dn * dn;

    uint2 sv = h0[(size_t)node * 16 + hl];
    float2 s0 = __half22float2(*reinterpret_cast<__half2*>(&sv.x));
    float2 s1 = __half22float2(*reinterpret_cast<__half2*>(&sv.y));
    float a0 = sw * s0.x, a1 = sw * s0.y, a2 = sw * s1.x, a3 = sw * s1.y;

    int beg = g_rowptr[node];
    int end = g_rowptr[node + 1];

    #pragma unroll 4
    for (int e = beg; e < end; e++) {
        int2  ed = __ldg(&g_edge[e]);
        float ww = __int_as_float(ed.y);
        uint2 hv = __ldg(&h0[(size_t)ed.x * 16 + hl]);
        float2 f0 = __half22float2(*reinterpret_cast<__half2*>(&hv.x));
        float2 f1 = __half22float2(*reinterpret_cast<__half2*>(&hv.y));
        a0 += ww * f0.x;
        a1 += ww * f0.y;
        a2 += ww * f1.x;
        a3 += ww * f1.y;
    }

    float4 bv = reinterpret_cast<const float4*>(bias)[hl];
    a0 += bv.x; a1 += bv.y; a2 += bv.z; a3 += bv.w;
    if (relu) {
        a0 = fmaxf(a0, 0.f); a1 = fmaxf(a1, 0.f);
        a2 = fmaxf(a2, 0.f); a3 = fmaxf(a3, 0.f);
    }
    reinterpret_cast<float4*>(g_h1)[(size_t)node * 16 + hl] =
        make_float4(a0, a1, a2, a3);
}

// ---------------- fused pooling + MLP head ----------------
__global__ __launch_bounds__(256) void pool_head_kernel(
        const int* __restrict__ batch,
        const float* __restrict__ lin1_w, const float* __restrict__ lin1_b,
        const float* __restrict__ lin2_w, const float* __restrict__ lin2_b,
        const float* __restrict__ lin3_w, const float* __restrict__ lin3_b,
        float* __restrict__ out) {
    int g = blockIdx.x;
    int tid = threadIdx.x;
    __shared__ int s_se[2];

    if (tid < 2) {
        int target = g + tid;
        int lo = 0, hi = NN;
        while (lo < hi) {
            int mid = (lo + hi) >> 1;
            if (__ldg(&batch[mid]) < target) lo = mid + 1;
            else hi = mid;
        }
        s_se[tid] = lo;
    }
    __syncthreads();
    int start = s_se[0], end = s_se[1];

    int sub = tid >> 6;
    int d   = tid & 63;

    float sum = 0.f, mx = -FLT_MAX;
    for (int n = start + sub; n < end; n += 4) {
        float v = g_h1[(size_t)n * 64 + d];
        sum += v;
        mx = fmaxf(mx, v);
    }

    __shared__ float ssum[4][64];
    __shared__ float smax[4][64];
    __shared__ float feat[128];
    __shared__ float s1[64];
    __shared__ float s2[64];
    __shared__ float red[64];

    ssum[sub][d] = sum;
    smax[sub][d] = mx;
    __syncthreads();

    if (tid < 64) {
        feat[d]      = ssum[0][d] + ssum[1][d] + ssum[2][d] + ssum[3][d];
        feat[64 + d] = fmaxf(fmaxf(smax[0][d], smax[1][d]),
                             fmaxf(smax[2][d], smax[3][d]));
    }
    __syncthreads();

    if (tid < 64) {
        float a = lin1_b[d];
        #pragma unroll 8
        for (int k = 0; k < 128; k++) a += feat[k] * lin1_w[k * 64 + d];
        s1[d] = fmaxf(a, 0.f);
    }
    __syncthreads();
    if (tid < 64) {
        float b = lin2_b[d];
        #pragma unroll 8
        for (int k = 0; k < 64; k++) b += s1[k] * lin2_w[k * 64 + d];
        s2[d] = fmaxf(b, 0.f);
        red[d] = s2[d] * lin3_w[d];
    }
    __syncthreads();
    if (tid < 32) {
        float v = red[tid] + red[tid + 32];
        #pragma unroll
        for (int off = 16; off > 0; off >>= 1)
            v += __shfl_down_sync(0xFFFFFFFF, v, off);
        if (tid == 0) out[g] = v + lin3_b[0];
    }
}

// ---------------- launch ----------------
#define SMEM_G64  (64 * 32 * 8 + 128 * 65 * 4)
#define SMEM_G128 (128 * 32 * 8 + 128 * 129 * 4)

extern "C" void kernel_launch(void* const* d_in, const int* in_sizes, int n_in,
                              void* d_out, int out_size) {
    const float* x      = (const float*)d_in[0];
    const int*   ei     = (const int*)d_in[1];
    const int*   batch  = (const int*)d_in[2];
    const float* W_in   = (const float*)d_in[3];
    const float* b_in   = (const float*)d_in[4];
    const float* W_hid  = (const float*)d_in[5];
    const float* b_hid  = (const float*)d_in[6];
    const float* lin1_w = (const float*)d_in[7];
    const float* lin1_b = (const float*)d_in[8];
    const float* lin2_w = (const float*)d_in[9];
    const float* lin2_b = (const float*)d_in[10];
    const float* lin3_w = (const float*)d_in[11];
    const float* lin3_b = (const float*)d_in[12];
    float* out = (float*)d_out;

    cudaFuncSetAttribute(gemm_kernel<CINC, true>,
                         cudaFuncAttributeMaxDynamicSharedMemorySize, SMEM_G128);
    cudaFuncSetAttribute(gemm_kernel<DD, false>,
                         cudaFuncAttributeMaxDynamicSharedMemorySize, SMEM_G64);

    // CSR build
    zero_deg_kernel<<<(NN + 255) / 256, 256>>>();
    count_deg_kernel<<<(EE + 255) / 256, 256>>>(ei);
    scanAB_kernel<<<NB_SCAN, 1024>>>();
    scanC_kernel<<<NB_SCAN, 1024>>>();
    scatter_kernel<<<(EE + 255) / 256, 256>>>(ei);

    const int gemm_blocks = NN / 128;
    const int agg_blocks  = (NN / 2 + 7) / 8;   // 2 nodes/warp, 8 warps/block

    gemm_kernel<CINC, true><<<gemm_blocks, 128, SMEM_G128>>>(x, W_in);
    aggregate_kernel<<<agg_blocks, 256>>>(b_in, 1);

    for (int i = 0; i < NHID; i++) {
        gemm_kernel<DD, false><<<gemm_blocks, 128, SMEM_G64>>>(
            nullptr, W_hid + (size_t)i * DD * DD);
        aggregate_kernel<<<agg_blocks, 256>>>(b_hid + (size_t)i * DD,
                                              (i < NHID - 1) ? 1 : 0);
    }

    pool_head_kernel<<<GG, 256>>>(batch, lin1_w, lin1_b, lin2_w, lin2_b,
                                  lin3_w, lin3_b, out);
}